// round 14
// baseline (speedup 1.0000x reference)
#include <cuda_runtime.h>
#include <cuda_fp16.h>
#include <cstdint>

// Problem constants
#define B_ 8
#define S_ 1024
#define D_ 1024
#define M_TOT (B_ * S_)   // 8192

// Scratch (allocation-free rule: __device__ globals)
// g_Q/g_K/g_V sized as float but used as fp16 (half the space).
__device__ float  g_Q[B_ * S_ * D_];
__device__ float  g_K[B_ * S_ * D_];
__device__ float  g_V[B_ * S_ * D_];
__device__ __half g_q16[B_ * S_ * D_];
__device__ __half g_k16[B_ * S_ * D_];
__device__ __half g_v16[B_ * S_ * D_];
__device__ __half g_a16[B_ * S_ * D_];
__device__ __half g_wq16[D_ * D_];
__device__ __half g_wk16[D_ * D_];
__device__ __half g_wv16[D_ * D_];
__device__ __half g_wo16[D_ * D_];

// ---------------------------------------------------------------------------
// Helpers
// ---------------------------------------------------------------------------
__device__ __forceinline__ uint32_t smem_u32(const void* p) {
    uint32_t a;
    asm("{ .reg .u64 t; cvta.to.shared.u64 t, %1; cvt.u32.u64 %0, t; }"
        : "=r"(a) : "l"(p));
    return a;
}

__device__ __forceinline__ float2 h2f(uint32_t h) {
    __half2 hh = *(__half2*)&h;
    return __half22float2(hh);
}
__device__ __forceinline__ uint32_t f2h(float lo, float hi) {
    uint32_t r;
    asm("cvt.rn.f16x2.f32 %0, %1, %2;" : "=r"(r) : "f"(hi), "f"(lo));
    return r;
}

#define LDSM4(r, addr)                                                        \
    asm volatile("ldmatrix.sync.aligned.m8n8.x4.shared.b16 "                  \
                 "{%0, %1, %2, %3}, [%4];"                                    \
                 : "=r"((r)[0]), "=r"((r)[1]), "=r"((r)[2]), "=r"((r)[3])     \
                 : "r"(addr))

#define LDSM4T(r, addr)                                                       \
    asm volatile("ldmatrix.sync.aligned.m8n8.x4.trans.shared.b16 "            \
                 "{%0, %1, %2, %3}, [%4];"                                    \
                 : "=r"((r)[0]), "=r"((r)[1]), "=r"((r)[2]), "=r"((r)[3])     \
                 : "r"(addr))

#define MMA16816F16(d, a, b)                                                  \
    asm volatile("mma.sync.aligned.m16n8k16.row.col.f32.f16.f16.f32 "         \
                 "{%0, %1, %2, %3}, {%4, %5, %6, %7}, {%8, %9}, "             \
                 "{%0, %1, %2, %3};"                                          \
                 : "+f"((d)[0]), "+f"((d)[1]), "+f"((d)[2]), "+f"((d)[3])     \
                 : "r"((a)[0]), "r"((a)[1]), "r"((a)[2]), "r"((a)[3]),        \
                   "r"((b)[0]), "r"((b)[1]))

#define CP_ASYNC16(dst, src)                                                  \
    asm volatile("cp.async.cg.shared.global [%0], [%1], 16;"                  \
                 :: "r"(dst), "l"(src) : "memory")
#define CP_COMMIT() asm volatile("cp.async.commit_group;" ::: "memory")
#define CP_WAIT2()  asm volatile("cp.async.wait_group 2;" ::: "memory")

// ---------------------------------------------------------------------------
// fp32 -> fp16 pre-conversion: ALL 7 tensors in ONE launch.
// blockIdx.z selects tensor via scalar ternaries (uniform, no param-array
// spill). z 0..2 = q/k/v (nIn4 float4), z 3..6 = weights (nW4); weight
// slices early-exit beyond their range.
// ---------------------------------------------------------------------------
__global__ void cvt_all(
    const float4* i0, const float4* i1, const float4* i2,
    const float4* i3, const float4* i4, const float4* i5, const float4* i6,
    uint2* o0, uint2* o1, uint2* o2,
    uint2* o3, uint2* o4, uint2* o5, uint2* o6,
    int nIn4, int nW4)
{
    const unsigned z = blockIdx.z;
    const float4* in =
        (z == 0) ? i0 : (z == 1) ? i1 : (z == 2) ? i2 :
        (z == 3) ? i3 : (z == 4) ? i4 : (z == 5) ? i5 : i6;
    uint2* out =
        (z == 0) ? o0 : (z == 1) ? o1 : (z == 2) ? o2 :
        (z == 3) ? o3 : (z == 4) ? o4 : (z == 5) ? o5 : o6;
    const int n4 = (z < 3) ? nIn4 : nW4;

    int i = blockIdx.x * blockDim.x + threadIdx.x;
    if (i < n4) {
        float4 v = in[i];
        out[i] = make_uint2(f2h(v.x, v.y), f2h(v.z, v.w));
    }
}

// ---------------------------------------------------------------------------
// fp16 HMMA GEMM body (unchanged — at measured mma.sync rate cap)
// ---------------------------------------------------------------------------
#define ROWB 80
#define TILE_B (128 * ROWB)
#define STAGE_B (2 * TILE_B)
#define NSTAGE 4
#define GEMM_SMEM (NSTAGE * STAGE_B)  // 81920 bytes
#define NCH (D_ / 32)

template <int SIG>
__device__ __forceinline__ void gemm_body(
    const __half* __restrict__ A, const __half* __restrict__ W,
    const float* __restrict__ bias, void* __restrict__ Cv, char* dsm)
{
    const uint32_t s0 = smem_u32(dsm);

    const int t    = threadIdx.x;
    const int warp = t >> 5;
    const int lane = t & 31;
    const int bm   = blockIdx.y * 128;
    const int bn   = blockIdx.x * 128;
    const int wm   = (warp & 3) * 32;
    const int wn   = (warp >> 2) * 32;

    const int crow = t >> 2;
    const int cseg = t & 3;
    const __half* gA = A + (size_t)(bm + crow) * D_ + cseg * 8;
    const __half* gW = W + (size_t)(bn + crow) * D_ + cseg * 8;
    const uint32_t cdst = (uint32_t)crow * ROWB + cseg * 16;

    const uint32_t a_off = (uint32_t)(wm + (lane & 15)) * ROWB + ((lane >> 4) << 4);
    const uint32_t w_off =
        (uint32_t)(wn + ((lane >> 4) << 3) + (lane & 7)) * ROWB + (((lane >> 3) & 1) << 4);

    float acc[2][4][4];
#pragma unroll
    for (int mt = 0; mt < 2; mt++)
#pragma unroll
        for (int nt = 0; nt < 4; nt++)
#pragma unroll
            for (int i = 0; i < 4; i++) acc[mt][nt][i] = 0.f;

#pragma unroll
    for (int st = 0; st < NSTAGE - 1; st++) {
        const uint32_t sb = s0 + st * STAGE_B;
        CP_ASYNC16(sb + cdst,          gA + st * 32);
        CP_ASYNC16(sb + TILE_B + cdst, gW + st * 32);
        CP_COMMIT();
    }

#pragma unroll 1
    for (int ch = 0; ch < NCH; ch++) {
        CP_WAIT2();
        __syncthreads();

        if (ch + NSTAGE - 1 < NCH) {
            const uint32_t sb = s0 + (uint32_t)((ch + NSTAGE - 1) & (NSTAGE - 1)) * STAGE_B;
            CP_ASYNC16(sb + cdst,          gA + (ch + NSTAGE - 1) * 32);
            CP_ASYNC16(sb + TILE_B + cdst, gW + (ch + NSTAGE - 1) * 32);
        }
        CP_COMMIT();

        const uint32_t cur = s0 + (uint32_t)(ch & (NSTAGE - 1)) * STAGE_B;
        const uint32_t cA = cur, cW = cur + TILE_B;

        uint32_t av0[2][4], wv0[2][4], av1[2][4], wv1[2][4];
        LDSM4(av0[0], cA + a_off);
        LDSM4(av0[1], cA + a_off + 16 * ROWB);
        LDSM4(wv0[0], cW + w_off);
        LDSM4(wv0[1], cW + w_off + 16 * ROWB);
        LDSM4(av1[0], cA + a_off + 32);
        LDSM4(av1[1], cA + a_off + 16 * ROWB + 32);
        LDSM4(wv1[0], cW + w_off + 32);
        LDSM4(wv1[1], cW + w_off + 16 * ROWB + 32);

#pragma unroll
        for (int mt = 0; mt < 2; mt++)
#pragma unroll
            for (int nt = 0; nt < 4; nt++)
                MMA16816F16(acc[mt][nt], av0[mt], (&wv0[nt >> 1][(nt & 1) * 2]));
#pragma unroll
        for (int mt = 0; mt < 2; mt++)
#pragma unroll
            for (int nt = 0; nt < 4; nt++)
                MMA16816F16(acc[mt][nt], av1[mt], (&wv1[nt >> 1][(nt & 1) * 2]));
    }

    const int er0 = bm + wm + (lane >> 2);
    const int ec0 = bn + wn + (lane & 3) * 2;

    float2 bb[4];
#pragma unroll
    for (int nt = 0; nt < 4; nt++)
        bb[nt] = *(const float2*)&bias[ec0 + nt * 8];

#pragma unroll
    for (int mt = 0; mt < 2; mt++) {
#pragma unroll
        for (int nt = 0; nt < 4; nt++) {
#pragma unroll
            for (int h = 0; h < 2; h++) {
                float2 v;
                v.x = acc[mt][nt][h * 2 + 0] + bb[nt].x;
                v.y = acc[mt][nt][h * 2 + 1] + bb[nt].y;
                const size_t idx = (size_t)(er0 + mt * 16 + h * 8) * D_ + ec0 + nt * 8;
                if (SIG) {
                    v.x = 1.f / (1.f + __expf(-v.x));
                    v.y = 1.f / (1.f + __expf(-v.y));
                    *(float2*)((float*)Cv + idx) = v;
                } else {
                    *(uint32_t*)((__half*)Cv + idx) = f2h(v.x, v.y);
                }
            }
        }
    }
}

__global__ void __launch_bounds__(512) gemm_qkv(
    const __half* A0, const __half* W0, const float* b0, __half* C0,
    const __half* A1, const __half* W1, const float* b1, __half* C1,
    const __half* A2, const __half* W2, const float* b2, __half* C2)
{
    extern __shared__ __align__(128) char dsm[];
    const unsigned z = blockIdx.z;
    const __half* A = (z == 0) ? A0 : (z == 1) ? A1 : A2;
    const __half* W = (z == 0) ? W0 : (z == 1) ? W1 : W2;
    const float*  b = (z == 0) ? b0 : (z == 1) ? b1 : b2;
    __half*       C = (z == 0) ? C0 : (z == 1) ? C1 : C2;
    gemm_body<0>(A, W, b, C, dsm);
}

__global__ void __launch_bounds__(512) gemm_o(
    const __half* __restrict__ A, const __half* __restrict__ W,
    const float* __restrict__ bias, float* __restrict__ C)
{
    extern __shared__ __align__(128) char dsm[];
    gemm_body<1>(A, W, bias, C, dsm);
}

// ---------------------------------------------------------------------------
// HMMA attention middle stage (R13, proven). 256 threads, one CTA per s.
// ---------------------------------------------------------------------------
#define QRS 144
#define QB_BYTES (16 * QRS)
#define ESRS 144
#define ESB_BYTES (64 * ESRS)
#define ES_TOT (8 * ESB_BYTES)
#define Q_OFF  ES_TOT
#define K_OFF  (Q_OFF + 8 * QB_BYTES)
#define ATTN_SMEM (K_OFF + 8 * QB_BYTES)  // 110592

__global__ void __launch_bounds__(256) attn_kernel()
{
    extern __shared__ __align__(16) char asmb[];
    const uint32_t sb = smem_u32(asmb);
    const uint32_t ES0 = sb;
    const uint32_t Q0  = sb + Q_OFF;
    const uint32_t K0  = sb + K_OFF;
    const uint32_t V0  = Q0;

    const int s    = blockIdx.x;
    const int t    = threadIdx.x;
    const int w    = t >> 5;
    const int lane = t & 31;

    const __half* Qg = (const __half*)g_Q;
    const __half* Kg = (const __half*)g_K;
    const __half* Vg = (const __half*)g_V;

    for (int u = t; u < 2048; u += 256) {
        const int isK  = u >> 10;
        const int v    = u & 1023;
        const int b    = v >> 7;
        const int h    = (v & 127) >> 3;
        const int pseg = v & 7;
        const size_t gi = ((size_t)b * S_ + s) * 128 + h * 8 + pseg;
        uint4 val = isK ? ((const uint4*)Kg)[gi] : ((const uint4*)Qg)[gi];
        char* dst = asmb + (isK ? K_OFF : Q_OFF) + b * QB_BYTES + h * QRS + pseg * 16;
        *(uint4*)dst = val;
    }
    __syncthreads();

    const int p0 = (w & 3) * 16;
    const int q0 = (w >> 2) * 32;

    const uint32_t krA  = (uint32_t)((lane & 7) + ((lane >> 4) << 3));
    const uint32_t caA  = (uint32_t)(p0 + ((lane >> 3) & 1) * 8) * 2;
    const uint32_t krB  = (uint32_t)((lane & 7) + ((lane >> 3) & 1) * 8);
    const uint32_t cbB  = (uint32_t)((lane >> 4) * 8) * 2;

    const int row0 = p0 + (lane >> 2);
    const int colq = q0 + (lane & 3) * 2;

    float denom[4][4];
#pragma unroll
    for (int nt = 0; nt < 4; nt++)
#pragma unroll
        for (int i = 0; i < 4; i++) denom[nt][i] = 0.f;

#pragma unroll 1
    for (int b = 0; b < 8; b++) {
        const uint32_t Qb = Q0 + b * QB_BYTES;
        const uint32_t Kb = K0 + b * QB_BYTES;
        char* ESp = asmb + b * ESB_BYTES;

        uint32_t afr[4];
        LDSM4T(afr, Qb + krA * QRS + caA);
        uint32_t bfr[2][4];
        LDSM4T(bfr[0], Kb + krB * QRS + (uint32_t)q0 * 2 + cbB);
        LDSM4T(bfr[1], Kb + krB * QRS + (uint32_t)(q0 + 16) * 2 + cbB);

        float acc[4][4];
#pragma unroll
        for (int nt = 0; nt < 4; nt++)
#pragma unroll
            for (int i = 0; i < 4; i++) acc[nt][i] = 0.f;
#pragma unroll
        for (int nt = 0; nt < 4; nt++)
            MMA16816F16(acc[nt], afr, (&bfr[nt >> 1][(nt & 1) * 2]));

#pragma unroll
        for (int nt = 0; nt < 4; nt++) {
            float e0 = __expf(acc[nt][0] * 0.125f);
            float e1 = __expf(acc[nt][1] * 0.125f);
            float e2 = __expf(acc[nt][2] * 0.125f);
            float e3 = __expf(acc[nt][3] * 0.125f);
            denom[nt][0] += e0; denom[nt][1] += e1;
            denom[nt][2] += e2; denom[nt][3] += e3;
            *(uint32_t*)(ESp + row0 * ESRS + (colq + nt * 8) * 2)       = f2h(e0, e1);
            *(uint32_t*)(ESp + (row0 + 8) * ESRS + (colq + nt * 8) * 2) = f2h(e2, e3);
        }
    }

    float rd[4][4];
#pragma unroll
    for (int nt = 0; nt < 4; nt++)
#pragma unroll
        for (int i = 0; i < 4; i++) rd[nt][i] = 1.f / denom[nt][i];

    __syncthreads();

    for (int u = t; u < 1024; u += 256) {
        const int b    = u >> 7;
        const int h    = (u & 127) >> 3;
        const int pseg = u & 7;
        const size_t gi = ((size_t)b * S_ + s) * 128 + h * 8 + pseg;
        uint4 val = ((const uint4*)Vg)[gi];
        *(uint4*)(asmb + Q_OFF + b * QB_BYTES + h * QRS + pseg * 16) = val;
    }

#pragma unroll 1
    for (int b = 0; b < 8; b++) {
        char* ESp = asmb + b * ESB_BYTES;
#pragma unroll
        for (int nt = 0; nt < 4; nt++) {
            uint32_t* a0 = (uint32_t*)(ESp + row0 * ESRS + (colq + nt * 8) * 2);
            uint32_t* a1 = (uint32_t*)(ESp + (row0 + 8) * ESRS + (colq + nt * 8) * 2);
            float2 v0 = h2f(*a0), v1 = h2f(*a1);
            *a0 = f2h(v0.x * rd[nt][0], v0.y * rd[nt][1]);
            *a1 = f2h(v1.x * rd[nt][2], v1.y * rd[nt][3]);
        }
    }
    __syncthreads();

    {
        const uint32_t Vb  = V0 + (uint32_t)w * QB_BYTES;
        const uint32_t ESb = ES0 + (uint32_t)w * ESB_BYTES;

        const uint32_t aoff = (uint32_t)(lane & 15) * QRS + ((lane >> 4) << 4);
        const uint32_t boff = (uint32_t)(((lane >> 4) << 3) + (lane & 7)) * ESRS +
                              (((lane >> 3) & 1) << 4);

        float acc2[8][4];
#pragma unroll
        for (int nt = 0; nt < 8; nt++)
#pragma unroll
            for (int i = 0; i < 4; i++) acc2[nt][i] = 0.f;

#pragma unroll
        for (int ks = 0; ks < 4; ks++) {
            uint32_t av[4];
            LDSM4(av, Vb + aoff + ks * 32);
            uint32_t bv[4][4];
#pragma unroll
            for (int g = 0; g < 4; g++)
                LDSM4(bv[g], ESb + boff + (uint32_t)g * 16 * ESRS + ks * 32);
#pragma unroll
            for (int nt = 0; nt < 8; nt++)
                MMA16816F16(acc2[nt], av, (&bv[nt >> 1][(nt & 1) * 2]));
        }

        __half* ob = g_a16 + ((size_t)w * S_ + s) * D_;
        const int hr = lane >> 2;
        const int pc = (lane & 3) * 2;
#pragma unroll
        for (int nt = 0; nt < 8; nt++) {
            *(uint32_t*)(ob + hr * 64 + nt * 8 + pc)       = f2h(acc2[nt][0], acc2[nt][1]);
            *(uint32_t*)(ob + (hr + 8) * 64 + nt * 8 + pc) = f2h(acc2[nt][2], acc2[nt][3]);
        }
    }
}

// ---------------------------------------------------------------------------
extern "C" void kernel_launch(void* const* d_in, const int* in_sizes, int n_in,
                              void* d_out, int out_size)
{
    const float* query = (const float*)d_in[0];
    const float* key   = (const float*)d_in[1];
    const float* value = (const float*)d_in[2];
    const float* Wq    = (const float*)d_in[3];
    const float* bq    = (const float*)d_in[4];
    const float* Wk    = (const float*)d_in[5];
    const float* bk    = (const float*)d_in[6];
    const float* Wv    = (const float*)d_in[7];
    const float* bv    = (const float*)d_in[8];
    const float* Wo    = (const float*)d_in[9];
    const float* bo    = (const float*)d_in[10];
    float* out = (float*)d_out;

    float *gQ, *gK, *gV;
    __half *q16, *k16, *v16, *a16, *wq16, *wk16, *wv16, *wo16;
    cudaGetSymbolAddress((void**)&gQ, g_Q);
    cudaGetSymbolAddress((void**)&gK, g_K);
    cudaGetSymbolAddress((void**)&gV, g_V);
    cudaGetSymbolAddress((void**)&q16, g_q16);
    cudaGetSymbolAddress((void**)&k16, g_k16);
    cudaGetSymbolAddress((void**)&v16, g_v16);
    cudaGetSymbolAddress((void**)&a16, g_a16);
    cudaGetSymbolAddress((void**)&wq16, g_wq16);
    cudaGetSymbolAddress((void**)&wk16, g_wk16);
    cudaGetSymbolAddress((void**)&wv16, g_wv16);
    cudaGetSymbolAddress((void**)&wo16, g_wo16);

    // All 7 conversions in ONE launch (z-indexed, scalar ternaries)
    const int nIn4 = (M_TOT * D_) / 4;    // 2,097,152
    const int nW4  = (D_ * D_) / 4;       // 262,144
    {
        dim3 g((nIn4 + 255) / 256, 1, 7);
        cvt_all<<<g, 256>>>(
            (const float4*)query, (const float4*)key, (const float4*)value,
            (const float4*)Wq, (const float4*)Wk, (const float4*)Wv,
            (const float4*)Wo,
            (uint2*)q16, (uint2*)k16, (uint2*)v16,
            (uint2*)wq16, (uint2*)wk16, (uint2*)wv16, (uint2*)wo16,
            nIn4, nW4);
    }

    cudaFuncSetAttribute(gemm_qkv,
                         cudaFuncAttributeMaxDynamicSharedMemorySize, GEMM_SMEM);
    cudaFuncSetAttribute(gemm_o,
                         cudaFuncAttributeMaxDynamicSharedMemorySize, GEMM_SMEM);
    cudaFuncSetAttribute(attn_kernel,
                         cudaFuncAttributeMaxDynamicSharedMemorySize, ATTN_SMEM);

    {
        dim3 grid(D_ / 128, M_TOT / 128, 3);   // (8, 64, 3)
        gemm_qkv<<<grid, 512, GEMM_SMEM>>>(
            q16, wq16, bq, (__half*)gQ,
            k16, wk16, bk, (__half*)gK,
            v16, wv16, bv, (__half*)gV);
    }

    attn_kernel<<<S_, 256, ATTN_SMEM>>>();

    {
        dim3 grid(D_ / 128, M_TOT / 128);      // (8, 64)
        gemm_o<<<grid, 512, GEMM_SMEM>>>(a16, wo16, bo, out);
    }
}

// round 15
// speedup vs baseline: 1.0482x; 1.0482x over previous
#include <cuda_runtime.h>
#include <cuda_fp16.h>
#include <cstdint>

// Problem constants
#define B_ 8
#define S_ 1024
#define D_ 1024
#define M_TOT (B_ * S_)   // 8192

// Scratch (allocation-free rule: __device__ globals)
// g_Q/g_K/g_V sized as float but used as fp16 (half the space).
__device__ float  g_Q[B_ * S_ * D_];
__device__ float  g_K[B_ * S_ * D_];
__device__ float  g_V[B_ * S_ * D_];
__device__ __half g_q16[B_ * S_ * D_];
__device__ __half g_k16[B_ * S_ * D_];
__device__ __half g_v16[B_ * S_ * D_];
__device__ __half g_a16[B_ * S_ * D_];
__device__ __half g_wq16[D_ * D_];
__device__ __half g_wk16[D_ * D_];
__device__ __half g_wv16[D_ * D_];
__device__ __half g_wo16[D_ * D_];

// ---------------------------------------------------------------------------
// Helpers
// ---------------------------------------------------------------------------
__device__ __forceinline__ uint32_t smem_u32(const void* p) {
    uint32_t a;
    asm("{ .reg .u64 t; cvta.to.shared.u64 t, %1; cvt.u32.u64 %0, t; }"
        : "=r"(a) : "l"(p));
    return a;
}

__device__ __forceinline__ float2 h2f(uint32_t h) {
    __half2 hh = *(__half2*)&h;
    return __half22float2(hh);
}
__device__ __forceinline__ uint32_t f2h(float lo, float hi) {
    uint32_t r;
    asm("cvt.rn.f16x2.f32 %0, %1, %2;" : "=r"(r) : "f"(hi), "f"(lo));
    return r;
}

#define LDSM4(r, addr)                                                        \
    asm volatile("ldmatrix.sync.aligned.m8n8.x4.shared.b16 "                  \
                 "{%0, %1, %2, %3}, [%4];"                                    \
                 : "=r"((r)[0]), "=r"((r)[1]), "=r"((r)[2]), "=r"((r)[3])     \
                 : "r"(addr))

#define LDSM4T(r, addr)                                                       \
    asm volatile("ldmatrix.sync.aligned.m8n8.x4.trans.shared.b16 "            \
                 "{%0, %1, %2, %3}, [%4];"                                    \
                 : "=r"((r)[0]), "=r"((r)[1]), "=r"((r)[2]), "=r"((r)[3])     \
                 : "r"(addr))

#define MMA16816F16(d, a, b)                                                  \
    asm volatile("mma.sync.aligned.m16n8k16.row.col.f32.f16.f16.f32 "         \
                 "{%0, %1, %2, %3}, {%4, %5, %6, %7}, {%8, %9}, "             \
                 "{%0, %1, %2, %3};"                                          \
                 : "+f"((d)[0]), "+f"((d)[1]), "+f"((d)[2]), "+f"((d)[3])     \
                 : "r"((a)[0]), "r"((a)[1]), "r"((a)[2]), "r"((a)[3]),        \
                   "r"((b)[0]), "r"((b)[1]))

#define CP_ASYNC16(dst, src)                                                  \
    asm volatile("cp.async.cg.shared.global [%0], [%1], 16;"                  \
                 :: "r"(dst), "l"(src) : "memory")
#define CP_COMMIT() asm volatile("cp.async.commit_group;" ::: "memory")
#define CP_WAIT1()  asm volatile("cp.async.wait_group 1;" ::: "memory")

// ---------------------------------------------------------------------------
// fp32 -> fp16 pre-conversion: ALL 7 tensors in ONE launch (scalar ternaries)
// ---------------------------------------------------------------------------
__global__ void cvt_all(
    const float4* i0, const float4* i1, const float4* i2,
    const float4* i3, const float4* i4, const float4* i5, const float4* i6,
    uint2* o0, uint2* o1, uint2* o2,
    uint2* o3, uint2* o4, uint2* o5, uint2* o6,
    int nIn4, int nW4)
{
    const unsigned z = blockIdx.z;
    const float4* in =
        (z == 0) ? i0 : (z == 1) ? i1 : (z == 2) ? i2 :
        (z == 3) ? i3 : (z == 4) ? i4 : (z == 5) ? i5 : i6;
    uint2* out =
        (z == 0) ? o0 : (z == 1) ? o1 : (z == 2) ? o2 :
        (z == 3) ? o3 : (z == 4) ? o4 : (z == 5) ? o5 : o6;
    const int n4 = (z < 3) ? nIn4 : nW4;

    int i = blockIdx.x * blockDim.x + threadIdx.x;
    if (i < n4) {
        float4 v = in[i];
        out[i] = make_uint2(f2h(v.x, v.y), f2h(v.z, v.w));
    }
}

// ---------------------------------------------------------------------------
// fp16 HMMA GEMM body (NT), BK=64, 3-stage cp.async pipeline, 512 threads
// (16 warps, 4m x 4n, warp tile 32x32). Stage = 2 fp16 tiles of
// 128 rows x 64 cols, row stride 144B (conflict-free ldmatrix: banks 4r
// mod 32, 8-row phases tile exactly). 16 chunks -> 16 barriers (was 32).
// wait_group 1 keeps 2 chunks in flight. K-steps processed pairwise
// (load both pair's fragments, then MMA) per the R10-proven pattern.
// ---------------------------------------------------------------------------
#define ROWB 144
#define TILE_B (128 * ROWB)           // 18432 bytes per tile
#define STAGE_B (2 * TILE_B)          // 36864 bytes per stage
#define NSTAGE 3
#define GEMM_SMEM (NSTAGE * STAGE_B)  // 110592 bytes
#define NCH (D_ / 64)                 // 16 chunks

template <int SIG>
__device__ __forceinline__ void gemm_body(
    const __half* __restrict__ A, const __half* __restrict__ W,
    const float* __restrict__ bias, void* __restrict__ Cv, char* dsm)
{
    const uint32_t s0 = smem_u32(dsm);

    const int t    = threadIdx.x;
    const int warp = t >> 5;
    const int lane = t & 31;
    const int bm   = blockIdx.y * 128;
    const int bn   = blockIdx.x * 128;
    const int wm   = (warp & 3) * 32;
    const int wn   = (warp >> 2) * 32;

    // cp.async mapping: 1024 x 16B copies per tile; thread does 2 per tile
    int crow[2], cseg[2];
#pragma unroll
    for (int j = 0; j < 2; j++) {
        const int c = t + j * 512;
        crow[j] = c >> 3;             // 0..127
        cseg[j] = c & 7;              // 16B segment within 128B row
    }
    const __half* gA0 = A + (size_t)(bm + crow[0]) * D_ + cseg[0] * 8;
    const __half* gA1 = A + (size_t)(bm + crow[1]) * D_ + cseg[1] * 8;
    const __half* gW0 = W + (size_t)(bn + crow[0]) * D_ + cseg[0] * 8;
    const __half* gW1 = W + (size_t)(bn + crow[1]) * D_ + cseg[1] * 8;
    const uint32_t cd0 = (uint32_t)crow[0] * ROWB + cseg[0] * 16;
    const uint32_t cd1 = (uint32_t)crow[1] * ROWB + cseg[1] * 16;

    // ldmatrix lane addressing
    const uint32_t a_off = (uint32_t)(wm + (lane & 15)) * ROWB + ((lane >> 4) << 4);
    const uint32_t w_off =
        (uint32_t)(wn + ((lane >> 4) << 3) + (lane & 7)) * ROWB + (((lane >> 3) & 1) << 4);

    float acc[2][4][4];
#pragma unroll
    for (int mt = 0; mt < 2; mt++)
#pragma unroll
        for (int nt = 0; nt < 4; nt++)
#pragma unroll
            for (int i = 0; i < 4; i++) acc[mt][nt][i] = 0.f;

    // Prologue: issue chunks 0..1
#pragma unroll
    for (int st = 0; st < NSTAGE - 1; st++) {
        const uint32_t sb = s0 + st * STAGE_B;
        CP_ASYNC16(sb + cd0,          gA0 + st * 64);
        CP_ASYNC16(sb + cd1,          gA1 + st * 64);
        CP_ASYNC16(sb + TILE_B + cd0, gW0 + st * 64);
        CP_ASYNC16(sb + TILE_B + cd1, gW1 + st * 64);
        CP_COMMIT();
    }

    int stage = 0;
#pragma unroll 1
    for (int ch = 0; ch < NCH; ch++) {
        CP_WAIT1();           // chunk ch resident
        __syncthreads();      // visible to all; oldest stage free

        if (ch + NSTAGE - 1 < NCH) {
            int nst = stage + 2; if (nst >= NSTAGE) nst -= NSTAGE;
            const uint32_t sb = s0 + (uint32_t)nst * STAGE_B;
            const int ko = (ch + NSTAGE - 1) * 64;
            CP_ASYNC16(sb + cd0,          gA0 + ko);
            CP_ASYNC16(sb + cd1,          gA1 + ko);
            CP_ASYNC16(sb + TILE_B + cd0, gW0 + ko);
            CP_ASYNC16(sb + TILE_B + cd1, gW1 + ko);
        }
        CP_COMMIT();

        const uint32_t cur = s0 + (uint32_t)stage * STAGE_B;
        const uint32_t cA = cur, cW = cur + TILE_B;
        if (++stage >= NSTAGE) stage = 0;

        // 4 k-steps, processed in 2 pairs (frags for both loaded up front)
#pragma unroll
        for (int pr = 0; pr < 2; pr++) {
            const uint32_t k0 = pr * 64;          // bytes: ks*32
            uint32_t av0[2][4], wv0[2][4], av1[2][4], wv1[2][4];
            LDSM4(av0[0], cA + a_off + k0);
            LDSM4(av0[1], cA + a_off + 16 * ROWB + k0);
            LDSM4(wv0[0], cW + w_off + k0);
            LDSM4(wv0[1], cW + w_off + 16 * ROWB + k0);
            LDSM4(av1[0], cA + a_off + k0 + 32);
            LDSM4(av1[1], cA + a_off + 16 * ROWB + k0 + 32);
            LDSM4(wv1[0], cW + w_off + k0 + 32);
            LDSM4(wv1[1], cW + w_off + 16 * ROWB + k0 + 32);

#pragma unroll
            for (int mt = 0; mt < 2; mt++)
#pragma unroll
                for (int nt = 0; nt < 4; nt++)
                    MMA16816F16(acc[mt][nt], av0[mt], (&wv0[nt >> 1][(nt & 1) * 2]));
#pragma unroll
            for (int mt = 0; mt < 2; mt++)
#pragma unroll
                for (int nt = 0; nt < 4; nt++)
                    MMA16816F16(acc[mt][nt], av1[mt], (&wv1[nt >> 1][(nt & 1) * 2]));
        }
        __syncthreads();
    }

    // Epilogue: direct register -> gmem, bias (+sigmoid)
    const int er0 = bm + wm + (lane >> 2);
    const int ec0 = bn + wn + (lane & 3) * 2;

    float2 bb[4];
#pragma unroll
    for (int nt = 0; nt < 4; nt++)
        bb[nt] = *(const float2*)&bias[ec0 + nt * 8];

#pragma unroll
    for (int mt = 0; mt < 2; mt++) {
#pragma unroll
        for (int nt = 0; nt < 4; nt++) {
#pragma unroll
            for (int h = 0; h < 2; h++) {
                float2 v;
                v.x = acc[mt][nt][h * 2 + 0] + bb[nt].x;
                v.y = acc[mt][nt][h * 2 + 1] + bb[nt].y;
                const size_t idx = (size_t)(er0 + mt * 16 + h * 8) * D_ + ec0 + nt * 8;
                if (SIG) {
                    v.x = 1.f / (1.f + __expf(-v.x));
                    v.y = 1.f / (1.f + __expf(-v.y));
                    *(float2*)((float*)Cv + idx) = v;
                } else {
                    *(uint32_t*)((__half*)Cv + idx) = f2h(v.x, v.y);
                }
            }
        }
    }
}

__global__ void __launch_bounds__(512) gemm_qkv(
    const __half* A0, const __half* W0, const float* b0, __half* C0,
    const __half* A1, const __half* W1, const float* b1, __half* C1,
    const __half* A2, const __half* W2, const float* b2, __half* C2)
{
    extern __shared__ __align__(128) char dsm[];
    const unsigned z = blockIdx.z;
    const __half* A = (z == 0) ? A0 : (z == 1) ? A1 : A2;
    const __half* W = (z == 0) ? W0 : (z == 1) ? W1 : W2;
    const float*  b = (z == 0) ? b0 : (z == 1) ? b1 : b2;
    __half*       C = (z == 0) ? C0 : (z == 1) ? C1 : C2;
    gemm_body<0>(A, W, b, C, dsm);
}

__global__ void __launch_bounds__(512) gemm_o(
    const __half* __restrict__ A, const __half* __restrict__ W,
    const float* __restrict__ bias, float* __restrict__ C)
{
    extern __shared__ __align__(128) char dsm[];
    gemm_body<1>(A, W, bias, C, dsm);
}

// ---------------------------------------------------------------------------
// HMMA attention middle stage (R13, proven). 256 threads, one CTA per s.
// ---------------------------------------------------------------------------
#define QRS 144
#define QB_BYTES (16 * QRS)
#define ESRS 144
#define ESB_BYTES (64 * ESRS)
#define ES_TOT (8 * ESB_BYTES)
#define Q_OFF  ES_TOT
#define K_OFF  (Q_OFF + 8 * QB_BYTES)
#define ATTN_SMEM (K_OFF + 8 * QB_BYTES)  // 110592

__global__ void __launch_bounds__(256) attn_kernel()
{
    extern __shared__ __align__(16) char asmb[];
    const uint32_t sb = smem_u32(asmb);
    const uint32_t ES0 = sb;
    const uint32_t Q0  = sb + Q_OFF;
    const uint32_t K0  = sb + K_OFF;
    const uint32_t V0  = Q0;

    const int s    = blockIdx.x;
    const int t    = threadIdx.x;
    const int w    = t >> 5;
    const int lane = t & 31;

    const __half* Qg = (const __half*)g_Q;
    const __half* Kg = (const __half*)g_K;
    const __half* Vg = (const __half*)g_V;

    for (int u = t; u < 2048; u += 256) {
        const int isK  = u >> 10;
        const int v    = u & 1023;
        const int b    = v >> 7;
        const int h    = (v & 127) >> 3;
        const int pseg = v & 7;
        const size_t gi = ((size_t)b * S_ + s) * 128 + h * 8 + pseg;
        uint4 val = isK ? ((const uint4*)Kg)[gi] : ((const uint4*)Qg)[gi];
        char* dst = asmb + (isK ? K_OFF : Q_OFF) + b * QB_BYTES + h * QRS + pseg * 16;
        *(uint4*)dst = val;
    }
    __syncthreads();

    const int p0 = (w & 3) * 16;
    const int q0 = (w >> 2) * 32;

    const uint32_t krA  = (uint32_t)((lane & 7) + ((lane >> 4) << 3));
    const uint32_t caA  = (uint32_t)(p0 + ((lane >> 3) & 1) * 8) * 2;
    const uint32_t krB  = (uint32_t)((lane & 7) + ((lane >> 3) & 1) * 8);
    const uint32_t cbB  = (uint32_t)((lane >> 4) * 8) * 2;

    const int row0 = p0 + (lane >> 2);
    const int colq = q0 + (lane & 3) * 2;

    float denom[4][4];
#pragma unroll
    for (int nt = 0; nt < 4; nt++)
#pragma unroll
        for (int i = 0; i < 4; i++) denom[nt][i] = 0.f;

#pragma unroll 1
    for (int b = 0; b < 8; b++) {
        const uint32_t Qb = Q0 + b * QB_BYTES;
        const uint32_t Kb = K0 + b * QB_BYTES;
        char* ESp = asmb + b * ESB_BYTES;

        uint32_t afr[4];
        LDSM4T(afr, Qb + krA * QRS + caA);
        uint32_t bfr[2][4];
        LDSM4T(bfr[0], Kb + krB * QRS + (uint32_t)q0 * 2 + cbB);
        LDSM4T(bfr[1], Kb + krB * QRS + (uint32_t)(q0 + 16) * 2 + cbB);

        float acc[4][4];
#pragma unroll
        for (int nt = 0; nt < 4; nt++)
#pragma unroll
            for (int i = 0; i < 4; i++) acc[nt][i] = 0.f;
#pragma unroll
        for (int nt = 0; nt < 4; nt++)
            MMA16816F16(acc[nt], afr, (&bfr[nt >> 1][(nt & 1) * 2]));

#pragma unroll
        for (int nt = 0; nt < 4; nt++) {
            float e0 = __expf(acc[nt][0] * 0.125f);
            float e1 = __expf(acc[nt][1] * 0.125f);
            float e2 = __expf(acc[nt][2] * 0.125f);
            float e3 = __expf(acc[nt][3] * 0.125f);
            denom[nt][0] += e0; denom[nt][1] += e1;
            denom[nt][2] += e2; denom[nt][3] += e3;
            *(uint32_t*)(ESp + row0 * ESRS + (colq + nt * 8) * 2)       = f2h(e0, e1);
            *(uint32_t*)(ESp + (row0 + 8) * ESRS + (colq + nt * 8) * 2) = f2h(e2, e3);
        }
    }

    float rd[4][4];
#pragma unroll
    for (int nt = 0; nt < 4; nt++)
#pragma unroll
        for (int i = 0; i < 4; i++) rd[nt][i] = 1.f / denom[nt][i];

    __syncthreads();

    for (int u = t; u < 1024; u += 256) {
        const int b    = u >> 7;
        const int h    = (u & 127) >> 3;
        const int pseg = u & 7;
        const size_t gi = ((size_t)b * S_ + s) * 128 + h * 8 + pseg;
        uint4 val = ((const uint4*)Vg)[gi];
        *(uint4*)(asmb + Q_OFF + b * QB_BYTES + h * QRS + pseg * 16) = val;
    }

#pragma unroll 1
    for (int b = 0; b < 8; b++) {
        char* ESp = asmb + b * ESB_BYTES;
#pragma unroll
        for (int nt = 0; nt < 4; nt++) {
            uint32_t* a0 = (uint32_t*)(ESp + row0 * ESRS + (colq + nt * 8) * 2);
            uint32_t* a1 = (uint32_t*)(ESp + (row0 + 8) * ESRS + (colq + nt * 8) * 2);
            float2 v0 = h2f(*a0), v1 = h2f(*a1);
            *a0 = f2h(v0.x * rd[nt][0], v0.y * rd[nt][1]);
            *a1 = f2h(v1.x * rd[nt][2], v1.y * rd[nt][3]);
        }
    }
    __syncthreads();

    {
        const uint32_t Vb  = V0 + (uint32_t)w * QB_BYTES;
        const uint32_t ESb = ES0 + (uint32_t)w * ESB_BYTES;

        const uint32_t aoff = (uint32_t)(lane & 15) * QRS + ((lane >> 4) << 4);
        const uint32_t boff = (uint32_t)(((lane >> 4) << 3) + (lane & 7)) * ESRS +
                              (((lane >> 3) & 1) << 4);

        float acc2[8][4];
#pragma unroll
        for (int nt = 0; nt < 8; nt++)
#pragma unroll
            for (int i = 0; i < 4; i++) acc2[nt][i] = 0.f;

#pragma unroll
        for (int ks = 0; ks < 4; ks++) {
            uint32_t av[4];
            LDSM4(av, Vb + aoff + ks * 32);
            uint32_t bv[4][4];
#pragma unroll
            for (int g = 0; g < 4; g++)
                LDSM4(bv[g], ESb + boff + (uint32_t)g * 16 * ESRS + ks * 32);
#pragma unroll
            for (int nt = 0; nt < 8; nt++)
                MMA16816F16(acc2[nt], av, (&bv[nt >> 1][(nt & 1) * 2]));
        }

        __half* ob = g_a16 + ((size_t)w * S_ + s) * D_;
        const int hr = lane >> 2;
        const int pc = (lane & 3) * 2;
#pragma unroll
        for (int nt = 0; nt < 8; nt++) {
            *(uint32_t*)(ob + hr * 64 + nt * 8 + pc)       = f2h(acc2[nt][0], acc2[nt][1]);
            *(uint32_t*)(ob + (hr + 8) * 64 + nt * 8 + pc) = f2h(acc2[nt][2], acc2[nt][3]);
        }
    }
}

// ---------------------------------------------------------------------------
extern "C" void kernel_launch(void* const* d_in, const int* in_sizes, int n_in,
                              void* d_out, int out_size)
{
    const float* query = (const float*)d_in[0];
    const float* key   = (const float*)d_in[1];
    const float* value = (const float*)d_in[2];
    const float* Wq    = (const float*)d_in[3];
    const float* bq    = (const float*)d_in[4];
    const float* Wk    = (const float*)d_in[5];
    const float* bk    = (const float*)d_in[6];
    const float* Wv    = (const float*)d_in[7];
    const float* bv    = (const float*)d_in[8];
    const float* Wo    = (const float*)d_in[9];
    const float* bo    = (const float*)d_in[10];
    float* out = (float*)d_out;

    float *gQ, *gK, *gV;
    __half *q16, *k16, *v16, *a16, *wq16, *wk16, *wv16, *wo16;
    cudaGetSymbolAddress((void**)&gQ, g_Q);
    cudaGetSymbolAddress((void**)&gK, g_K);
    cudaGetSymbolAddress((void**)&gV, g_V);
    cudaGetSymbolAddress((void**)&q16, g_q16);
    cudaGetSymbolAddress((void**)&k16, g_k16);
    cudaGetSymbolAddress((void**)&v16, g_v16);
    cudaGetSymbolAddress((void**)&a16, g_a16);
    cudaGetSymbolAddress((void**)&wq16, g_wq16);
    cudaGetSymbolAddress((void**)&wk16, g_wk16);
    cudaGetSymbolAddress((void**)&wv16, g_wv16);
    cudaGetSymbolAddress((void**)&wo16, g_wo16);

    // All 7 conversions in ONE launch
    const int nIn4 = (M_TOT * D_) / 4;
    const int nW4  = (D_ * D_) / 4;
    {
        dim3 g((nIn4 + 255) / 256, 1, 7);
        cvt_all<<<g, 256>>>(
            (const float4*)query, (const float4*)key, (const float4*)value,
            (const float4*)Wq, (const float4*)Wk, (const float4*)Wv,
            (const float4*)Wo,
            (uint2*)q16, (uint2*)k16, (uint2*)v16,
            (uint2*)wq16, (uint2*)wk16, (uint2*)wv16, (uint2*)wo16,
            nIn4, nW4);
    }

    cudaFuncSetAttribute(gemm_qkv,
                         cudaFuncAttributeMaxDynamicSharedMemorySize, GEMM_SMEM);
    cudaFuncSetAttribute(gemm_o,
                         cudaFuncAttributeMaxDynamicSharedMemorySize, GEMM_SMEM);
    cudaFuncSetAttribute(attn_kernel,
                         cudaFuncAttributeMaxDynamicSharedMemorySize, ATTN_SMEM);

    {
        dim3 grid(D_ / 128, M_TOT / 128, 3);   // (8, 64, 3)
        gemm_qkv<<<grid, 512, GEMM_SMEM>>>(
            q16, wq16, bq, (__half*)gQ,
            k16, wk16, bk, (__half*)gK,
            v16, wv16, bv, (__half*)gV);
    }

    attn_kernel<<<S_, 256, ATTN_SMEM>>>();

    {
        dim3 grid(D_ / 128, M_TOT / 128);      // (8, 64)
        gemm_o<<<grid, 512, GEMM_SMEM>>>(a16, wo16, bo, out);
    }
}

// round 16
// speedup vs baseline: 1.1231x; 1.0714x over previous
#include <cuda_runtime.h>
#include <cuda_fp16.h>
#include <cstdint>

// Problem constants
#define B_ 8
#define S_ 1024
#define D_ 1024
#define M_TOT (B_ * S_)   // 8192

// Scratch (allocation-free rule: __device__ globals)
// g_Q/g_K/g_V sized as float but used as fp16 (half the space).
__device__ float  g_Q[B_ * S_ * D_];
__device__ float  g_K[B_ * S_ * D_];
__device__ float  g_V[B_ * S_ * D_];
__device__ __half g_q16[B_ * S_ * D_];
__device__ __half g_k16[B_ * S_ * D_];
__device__ __half g_v16[B_ * S_ * D_];
__device__ __half g_a16[B_ * S_ * D_];
__device__ __half g_wq16[D_ * D_];
__device__ __half g_wk16[D_ * D_];
__device__ __half g_wv16[D_ * D_];
__device__ __half g_wo16[D_ * D_];

// ---------------------------------------------------------------------------
// Helpers
// ---------------------------------------------------------------------------
__device__ __forceinline__ uint32_t smem_u32(const void* p) {
    uint32_t a;
    asm("{ .reg .u64 t; cvta.to.shared.u64 t, %1; cvt.u32.u64 %0, t; }"
        : "=r"(a) : "l"(p));
    return a;
}

__device__ __forceinline__ float2 h2f(uint32_t h) {
    __half2 hh = *(__half2*)&h;
    return __half22float2(hh);
}
__device__ __forceinline__ uint32_t f2h(float lo, float hi) {
    uint32_t r;
    asm("cvt.rn.f16x2.f32 %0, %1, %2;" : "=r"(r) : "f"(hi), "f"(lo));
    return r;
}

#define LDSM4(r, addr)                                                        \
    asm volatile("ldmatrix.sync.aligned.m8n8.x4.shared.b16 "                  \
                 "{%0, %1, %2, %3}, [%4];"                                    \
                 : "=r"((r)[0]), "=r"((r)[1]), "=r"((r)[2]), "=r"((r)[3])     \
                 : "r"(addr))

#define LDSM4T(r, addr)                                                       \
    asm volatile("ldmatrix.sync.aligned.m8n8.x4.trans.shared.b16 "            \
                 "{%0, %1, %2, %3}, [%4];"                                    \
                 : "=r"((r)[0]), "=r"((r)[1]), "=r"((r)[2]), "=r"((r)[3])     \
                 : "r"(addr))

#define MMA16816F16(d, a, b)                                                  \
    asm volatile("mma.sync.aligned.m16n8k16.row.col.f32.f16.f16.f32 "         \
                 "{%0, %1, %2, %3}, {%4, %5, %6, %7}, {%8, %9}, "             \
                 "{%0, %1, %2, %3};"                                          \
                 : "+f"((d)[0]), "+f"((d)[1]), "+f"((d)[2]), "+f"((d)[3])     \
                 : "r"((a)[0]), "r"((a)[1]), "r"((a)[2]), "r"((a)[3]),        \
                   "r"((b)[0]), "r"((b)[1]))

#define CP_ASYNC16(dst, src)                                                  \
    asm volatile("cp.async.cg.shared.global [%0], [%1], 16;"                  \
                 :: "r"(dst), "l"(src) : "memory")
#define CP_COMMIT() asm volatile("cp.async.commit_group;" ::: "memory")
#define CP_WAIT1()  asm volatile("cp.async.wait_group 1;" ::: "memory")

// ---------------------------------------------------------------------------
// fp32 -> fp16 pre-conversion: ALL 7 tensors in ONE launch (scalar
// ternaries). 4 float4 per thread, loads front-batched (MLP=4) to cover
// DRAM latency; previous 1-load-1-store version was latency-bound.
// ---------------------------------------------------------------------------
__global__ void cvt_all(
    const float4* i0, const float4* i1, const float4* i2,
    const float4* i3, const float4* i4, const float4* i5, const float4* i6,
    uint2* o0, uint2* o1, uint2* o2,
    uint2* o3, uint2* o4, uint2* o5, uint2* o6,
    int nIn4, int nW4)
{
    const unsigned z = blockIdx.z;
    const float4* in =
        (z == 0) ? i0 : (z == 1) ? i1 : (z == 2) ? i2 :
        (z == 3) ? i3 : (z == 4) ? i4 : (z == 5) ? i5 : i6;
    uint2* out =
        (z == 0) ? o0 : (z == 1) ? o1 : (z == 2) ? o2 :
        (z == 3) ? o3 : (z == 4) ? o4 : (z == 5) ? o5 : o6;
    const int n4 = (z < 3) ? nIn4 : nW4;

    const int base = (blockIdx.x * blockDim.x) * 4 + threadIdx.x;
    if (base + 3 * 256 < n4) {
        float4 v0 = in[base];
        float4 v1 = in[base + 256];
        float4 v2 = in[base + 512];
        float4 v3 = in[base + 768];
        out[base]       = make_uint2(f2h(v0.x, v0.y), f2h(v0.z, v0.w));
        out[base + 256] = make_uint2(f2h(v1.x, v1.y), f2h(v1.z, v1.w));
        out[base + 512] = make_uint2(f2h(v2.x, v2.y), f2h(v2.z, v2.w));
        out[base + 768] = make_uint2(f2h(v3.x, v3.y), f2h(v3.z, v3.w));
    } else {
#pragma unroll
        for (int j = 0; j < 4; j++) {
            int i = base + j * 256;
            if (i < n4) {
                float4 v = in[i];
                out[i] = make_uint2(f2h(v.x, v.y), f2h(v.z, v.w));
            }
        }
    }
}

// ---------------------------------------------------------------------------
// fp16 HMMA GEMM body (NT), BK=64, 3-stage cp.async pipeline, 512 threads
// (16 warps, 4m x 4n, warp tile 32x32). Stage = 2 fp16 tiles of
// 128 rows x 64 cols, row stride 144B (conflict-free ldmatrix).
// ONE barrier per chunk: the top wait+sync already orders the
// overwrite-after-read hazard (cp.async issued at chunk ch targets the
// stage of chunk ch-1, whose LDSMs completed before every warp reached
// this barrier). Bottom barrier removed.
// ---------------------------------------------------------------------------
#define ROWB 144
#define TILE_B (128 * ROWB)           // 18432 bytes per tile
#define STAGE_B (2 * TILE_B)          // 36864 bytes per stage
#define NSTAGE 3
#define GEMM_SMEM (NSTAGE * STAGE_B)  // 110592 bytes
#define NCH (D_ / 64)                 // 16 chunks

template <int SIG>
__device__ __forceinline__ void gemm_body(
    const __half* __restrict__ A, const __half* __restrict__ W,
    const float* __restrict__ bias, void* __restrict__ Cv, char* dsm)
{
    const uint32_t s0 = smem_u32(dsm);

    const int t    = threadIdx.x;
    const int warp = t >> 5;
    const int lane = t & 31;
    const int bm   = blockIdx.y * 128;
    const int bn   = blockIdx.x * 128;
    const int wm   = (warp & 3) * 32;
    const int wn   = (warp >> 2) * 32;

    // cp.async mapping: 1024 x 16B copies per tile; thread does 2 per tile
    int crow[2], cseg[2];
#pragma unroll
    for (int j = 0; j < 2; j++) {
        const int c = t + j * 512;
        crow[j] = c >> 3;
        cseg[j] = c & 7;
    }
    const __half* gA0 = A + (size_t)(bm + crow[0]) * D_ + cseg[0] * 8;
    const __half* gA1 = A + (size_t)(bm + crow[1]) * D_ + cseg[1] * 8;
    const __half* gW0 = W + (size_t)(bn + crow[0]) * D_ + cseg[0] * 8;
    const __half* gW1 = W + (size_t)(bn + crow[1]) * D_ + cseg[1] * 8;
    const uint32_t cd0 = (uint32_t)crow[0] * ROWB + cseg[0] * 16;
    const uint32_t cd1 = (uint32_t)crow[1] * ROWB + cseg[1] * 16;

    const uint32_t a_off = (uint32_t)(wm + (lane & 15)) * ROWB + ((lane >> 4) << 4);
    const uint32_t w_off =
        (uint32_t)(wn + ((lane >> 4) << 3) + (lane & 7)) * ROWB + (((lane >> 3) & 1) << 4);

    float acc[2][4][4];
#pragma unroll
    for (int mt = 0; mt < 2; mt++)
#pragma unroll
        for (int nt = 0; nt < 4; nt++)
#pragma unroll
            for (int i = 0; i < 4; i++) acc[mt][nt][i] = 0.f;

#pragma unroll
    for (int st = 0; st < NSTAGE - 1; st++) {
        const uint32_t sb = s0 + st * STAGE_B;
        CP_ASYNC16(sb + cd0,          gA0 + st * 64);
        CP_ASYNC16(sb + cd1,          gA1 + st * 64);
        CP_ASYNC16(sb + TILE_B + cd0, gW0 + st * 64);
        CP_ASYNC16(sb + TILE_B + cd1, gW1 + st * 64);
        CP_COMMIT();
    }

    int stage = 0;
#pragma unroll 1
    for (int ch = 0; ch < NCH; ch++) {
        CP_WAIT1();           // chunk ch resident (this thread's groups)
        __syncthreads();      // all warps: data visible AND prior reads done

        if (ch + NSTAGE - 1 < NCH) {
            int nst = stage + 2; if (nst >= NSTAGE) nst -= NSTAGE;
            const uint32_t sb = s0 + (uint32_t)nst * STAGE_B;
            const int ko = (ch + NSTAGE - 1) * 64;
            CP_ASYNC16(sb + cd0,          gA0 + ko);
            CP_ASYNC16(sb + cd1,          gA1 + ko);
            CP_ASYNC16(sb + TILE_B + cd0, gW0 + ko);
            CP_ASYNC16(sb + TILE_B + cd1, gW1 + ko);
        }
        CP_COMMIT();

        const uint32_t cur = s0 + (uint32_t)stage * STAGE_B;
        const uint32_t cA = cur, cW = cur + TILE_B;
        if (++stage >= NSTAGE) stage = 0;

#pragma unroll
        for (int pr = 0; pr < 2; pr++) {
            const uint32_t k0 = pr * 64;
            uint32_t av0[2][4], wv0[2][4], av1[2][4], wv1[2][4];
            LDSM4(av0[0], cA + a_off + k0);
            LDSM4(av0[1], cA + a_off + 16 * ROWB + k0);
            LDSM4(wv0[0], cW + w_off + k0);
            LDSM4(wv0[1], cW + w_off + 16 * ROWB + k0);
            LDSM4(av1[0], cA + a_off + k0 + 32);
            LDSM4(av1[1], cA + a_off + 16 * ROWB + k0 + 32);
            LDSM4(wv1[0], cW + w_off + k0 + 32);
            LDSM4(wv1[1], cW + w_off + 16 * ROWB + k0 + 32);

#pragma unroll
            for (int mt = 0; mt < 2; mt++)
#pragma unroll
                for (int nt = 0; nt < 4; nt++)
                    MMA16816F16(acc[mt][nt], av0[mt], (&wv0[nt >> 1][(nt & 1) * 2]));
#pragma unroll
            for (int mt = 0; mt < 2; mt++)
#pragma unroll
                for (int nt = 0; nt < 4; nt++)
                    MMA16816F16(acc[mt][nt], av1[mt], (&wv1[nt >> 1][(nt & 1) * 2]));
        }
        // No bottom barrier: the next iteration's top __syncthreads orders
        // the overwrite of this stage (NSTAGE=3 gives one-stage slack).
    }

    const int er0 = bm + wm + (lane >> 2);
    const int ec0 = bn + wn + (lane & 3) * 2;

    float2 bb[4];
#pragma unroll
    for (int nt = 0; nt < 4; nt++)
        bb[nt] = *(const float2*)&bias[ec0 + nt * 8];

#pragma unroll
    for (int mt = 0; mt < 2; mt++) {
#pragma unroll
        for (int nt = 0; nt < 4; nt++) {
#pragma unroll
            for (int h = 0; h < 2; h++) {
                float2 v;
                v.x = acc[mt][nt][h * 2 + 0] + bb[nt].x;
                v.y = acc[mt][nt][h * 2 + 1] + bb[nt].y;
                const size_t idx = (size_t)(er0 + mt * 16 + h * 8) * D_ + ec0 + nt * 8;
                if (SIG) {
                    v.x = 1.f / (1.f + __expf(-v.x));
                    v.y = 1.f / (1.f + __expf(-v.y));
                    *(float2*)((float*)Cv + idx) = v;
                } else {
                    *(uint32_t*)((__half*)Cv + idx) = f2h(v.x, v.y);
                }
            }
        }
    }
}

__global__ void __launch_bounds__(512) gemm_qkv(
    const __half* A0, const __half* W0, const float* b0, __half* C0,
    const __half* A1, const __half* W1, const float* b1, __half* C1,
    const __half* A2, const __half* W2, const float* b2, __half* C2)
{
    extern __shared__ __align__(128) char dsm[];
    const unsigned z = blockIdx.z;
    const __half* A = (z == 0) ? A0 : (z == 1) ? A1 : A2;
    const __half* W = (z == 0) ? W0 : (z == 1) ? W1 : W2;
    const float*  b = (z == 0) ? b0 : (z == 1) ? b1 : b2;
    __half*       C = (z == 0) ? C0 : (z == 1) ? C1 : C2;
    gemm_body<0>(A, W, b, C, dsm);
}

__global__ void __launch_bounds__(512) gemm_o(
    const __half* __restrict__ A, const __half* __restrict__ W,
    const float* __restrict__ bias, float* __restrict__ C)
{
    extern __shared__ __align__(128) char dsm[];
    gemm_body<1>(A, W, bias, C, dsm);
}

// ---------------------------------------------------------------------------
// HMMA attention middle stage (R13, proven). 256 threads, one CTA per s.
// ---------------------------------------------------------------------------
#define QRS 144
#define QB_BYTES (16 * QRS)
#define ESRS 144
#define ESB_BYTES (64 * ESRS)
#define ES_TOT (8 * ESB_BYTES)
#define Q_OFF  ES_TOT
#define K_OFF  (Q_OFF + 8 * QB_BYTES)
#define ATTN_SMEM (K_OFF + 8 * QB_BYTES)  // 110592

__global__ void __launch_bounds__(256) attn_kernel()
{
    extern __shared__ __align__(16) char asmb[];
    const uint32_t sb = smem_u32(asmb);
    const uint32_t ES0 = sb;
    const uint32_t Q0  = sb + Q_OFF;
    const uint32_t K0  = sb + K_OFF;
    const uint32_t V0  = Q0;

    const int s    = blockIdx.x;
    const int t    = threadIdx.x;
    const int w    = t >> 5;
    const int lane = t & 31;

    const __half* Qg = (const __half*)g_Q;
    const __half* Kg = (const __half*)g_K;
    const __half* Vg = (const __half*)g_V;

    for (int u = t; u < 2048; u += 256) {
        const int isK  = u >> 10;
        const int v    = u & 1023;
        const int b    = v >> 7;
        const int h    = (v & 127) >> 3;
        const int pseg = v & 7;
        const size_t gi = ((size_t)b * S_ + s) * 128 + h * 8 + pseg;
        uint4 val = isK ? ((const uint4*)Kg)[gi] : ((const uint4*)Qg)[gi];
        char* dst = asmb + (isK ? K_OFF : Q_OFF) + b * QB_BYTES + h * QRS + pseg * 16;
        *(uint4*)dst = val;
    }
    __syncthreads();

    const int p0 = (w & 3) * 16;
    const int q0 = (w >> 2) * 32;

    const uint32_t krA  = (uint32_t)((lane & 7) + ((lane >> 4) << 3));
    const uint32_t caA  = (uint32_t)(p0 + ((lane >> 3) & 1) * 8) * 2;
    const uint32_t krB  = (uint32_t)((lane & 7) + ((lane >> 3) & 1) * 8);
    const uint32_t cbB  = (uint32_t)((lane >> 4) * 8) * 2;

    const int row0 = p0 + (lane >> 2);
    const int colq = q0 + (lane & 3) * 2;

    float denom[4][4];
#pragma unroll
    for (int nt = 0; nt < 4; nt++)
#pragma unroll
        for (int i = 0; i < 4; i++) denom[nt][i] = 0.f;

#pragma unroll 1
    for (int b = 0; b < 8; b++) {
        const uint32_t Qb = Q0 + b * QB_BYTES;
        const uint32_t Kb = K0 + b * QB_BYTES;
        char* ESp = asmb + b * ESB_BYTES;

        uint32_t afr[4];
        LDSM4T(afr, Qb + krA * QRS + caA);
        uint32_t bfr[2][4];
        LDSM4T(bfr[0], Kb + krB * QRS + (uint32_t)q0 * 2 + cbB);
        LDSM4T(bfr[1], Kb + krB * QRS + (uint32_t)(q0 + 16) * 2 + cbB);

        float acc[4][4];
#pragma unroll
        for (int nt = 0; nt < 4; nt++)
#pragma unroll
            for (int i = 0; i < 4; i++) acc[nt][i] = 0.f;
#pragma unroll
        for (int nt = 0; nt < 4; nt++)
            MMA16816F16(acc[nt], afr, (&bfr[nt >> 1][(nt & 1) * 2]));

#pragma unroll
        for (int nt = 0; nt < 4; nt++) {
            float e0 = __expf(acc[nt][0] * 0.125f);
            float e1 = __expf(acc[nt][1] * 0.125f);
            float e2 = __expf(acc[nt][2] * 0.125f);
            float e3 = __expf(acc[nt][3] * 0.125f);
            denom[nt][0] += e0; denom[nt][1] += e1;
            denom[nt][2] += e2; denom[nt][3] += e3;
            *(uint32_t*)(ESp + row0 * ESRS + (colq + nt * 8) * 2)       = f2h(e0, e1);
            *(uint32_t*)(ESp + (row0 + 8) * ESRS + (colq + nt * 8) * 2) = f2h(e2, e3);
        }
    }

    float rd[4][4];
#pragma unroll
    for (int nt = 0; nt < 4; nt++)
#pragma unroll
        for (int i = 0; i < 4; i++) rd[nt][i] = 1.f / denom[nt][i];

    __syncthreads();

    for (int u = t; u < 1024; u += 256) {
        const int b    = u >> 7;
        const int h    = (u & 127) >> 3;
        const int pseg = u & 7;
        const size_t gi = ((size_t)b * S_ + s) * 128 + h * 8 + pseg;
        uint4 val = ((const uint4*)Vg)[gi];
        *(uint4*)(asmb + Q_OFF + b * QB_BYTES + h * QRS + pseg * 16) = val;
    }

#pragma unroll 1
    for (int b = 0; b < 8; b++) {
        char* ESp = asmb + b * ESB_BYTES;
#pragma unroll
        for (int nt = 0; nt < 4; nt++) {
            uint32_t* a0 = (uint32_t*)(ESp + row0 * ESRS + (colq + nt * 8) * 2);
            uint32_t* a1 = (uint32_t*)(ESp + (row0 + 8) * ESRS + (colq + nt * 8) * 2);
            float2 v0 = h2f(*a0), v1 = h2f(*a1);
            *a0 = f2h(v0.x * rd[nt][0], v0.y * rd[nt][1]);
            *a1 = f2h(v1.x * rd[nt][2], v1.y * rd[nt][3]);
        }
    }
    __syncthreads();

    {
        const uint32_t Vb  = V0 + (uint32_t)w * QB_BYTES;
        const uint32_t ESb = ES0 + (uint32_t)w * ESB_BYTES;

        const uint32_t aoff = (uint32_t)(lane & 15) * QRS + ((lane >> 4) << 4);
        const uint32_t boff = (uint32_t)(((lane >> 4) << 3) + (lane & 7)) * ESRS +
                              (((lane >> 3) & 1) << 4);

        float acc2[8][4];
#pragma unroll
        for (int nt = 0; nt < 8; nt++)
#pragma unroll
            for (int i = 0; i < 4; i++) acc2[nt][i] = 0.f;

#pragma unroll
        for (int ks = 0; ks < 4; ks++) {
            uint32_t av[4];
            LDSM4(av, Vb + aoff + ks * 32);
            uint32_t bv[4][4];
#pragma unroll
            for (int g = 0; g < 4; g++)
                LDSM4(bv[g], ESb + boff + (uint32_t)g * 16 * ESRS + ks * 32);
#pragma unroll
            for (int nt = 0; nt < 8; nt++)
                MMA16816F16(acc2[nt], av, (&bv[nt >> 1][(nt & 1) * 2]));
        }

        __half* ob = g_a16 + ((size_t)w * S_ + s) * D_;
        const int hr = lane >> 2;
        const int pc = (lane & 3) * 2;
#pragma unroll
        for (int nt = 0; nt < 8; nt++) {
            *(uint32_t*)(ob + hr * 64 + nt * 8 + pc)       = f2h(acc2[nt][0], acc2[nt][1]);
            *(uint32_t*)(ob + (hr + 8) * 64 + nt * 8 + pc) = f2h(acc2[nt][2], acc2[nt][3]);
        }
    }
}

// ---------------------------------------------------------------------------
extern "C" void kernel_launch(void* const* d_in, const int* in_sizes, int n_in,
                              void* d_out, int out_size)
{
    const float* query = (const float*)d_in[0];
    const float* key   = (const float*)d_in[1];
    const float* value = (const float*)d_in[2];
    const float* Wq    = (const float*)d_in[3];
    const float* bq    = (const float*)d_in[4];
    const float* Wk    = (const float*)d_in[5];
    const float* bk    = (const float*)d_in[6];
    const float* Wv    = (const float*)d_in[7];
    const float* bv    = (const float*)d_in[8];
    const float* Wo    = (const float*)d_in[9];
    const float* bo    = (const float*)d_in[10];
    float* out = (float*)d_out;

    float *gQ, *gK, *gV;
    __half *q16, *k16, *v16, *a16, *wq16, *wk16, *wv16, *wo16;
    cudaGetSymbolAddress((void**)&gQ, g_Q);
    cudaGetSymbolAddress((void**)&gK, g_K);
    cudaGetSymbolAddress((void**)&gV, g_V);
    cudaGetSymbolAddress((void**)&q16, g_q16);
    cudaGetSymbolAddress((void**)&k16, g_k16);
    cudaGetSymbolAddress((void**)&v16, g_v16);
    cudaGetSymbolAddress((void**)&a16, g_a16);
    cudaGetSymbolAddress((void**)&wq16, g_wq16);
    cudaGetSymbolAddress((void**)&wk16, g_wk16);
    cudaGetSymbolAddress((void**)&wv16, g_wv16);
    cudaGetSymbolAddress((void**)&wo16, g_wo16);

    // All 7 conversions in ONE launch, 4 float4 per thread (MLP=4)
    const int nIn4 = (M_TOT * D_) / 4;
    const int nW4  = (D_ * D_) / 4;
    {
        dim3 g((nIn4 + 1023) / 1024, 1, 7);
        cvt_all<<<g, 256>>>(
            (const float4*)query, (const float4*)key, (const float4*)value,
            (const float4*)Wq, (const float4*)Wk, (const float4*)Wv,
            (const float4*)Wo,
            (uint2*)q16, (uint2*)k16, (uint2*)v16,
            (uint2*)wq16, (uint2*)wk16, (uint2*)wv16, (uint2*)wo16,
            nIn4, nW4);
    }

    cudaFuncSetAttribute(gemm_qkv,
                         cudaFuncAttributeMaxDynamicSharedMemorySize, GEMM_SMEM);
    cudaFuncSetAttribute(gemm_o,
                         cudaFuncAttributeMaxDynamicSharedMemorySize, GEMM_SMEM);
    cudaFuncSetAttribute(attn_kernel,
                         cudaFuncAttributeMaxDynamicSharedMemorySize, ATTN_SMEM);

    {
        dim3 grid(D_ / 128, M_TOT / 128, 3);   // (8, 64, 3)
        gemm_qkv<<<grid, 512, GEMM_SMEM>>>(
            q16, wq16, bq, (__half*)gQ,
            k16, wk16, bk, (__half*)gK,
            v16, wv16, bv, (__half*)gV);
    }

    attn_kernel<<<S_, 256, ATTN_SMEM>>>();

    {
        dim3 grid(D_ / 128, M_TOT / 128);      // (8, 64)
        gemm_o<<<grid, 512, GEMM_SMEM>>>(a16, wo16, bo, out);
    }
}